// round 8
// baseline (speedup 1.0000x reference)
#include <cuda_runtime.h>
#include <cuda_fp16.h>
#include <cstdint>

// ============================================================================
// SimpleRNN fused kernel R8: register-resident recurrence.
// Warp tile m32 x n128: the tanh'd C-fragment is repacked in-register as the
// A-fragment of the next step's hh GEMM (C->A layout identity for m16n8k16).
// No h SMEM round-trip, no barriers in the loop. x is loaded per-lane straight
// into A-fragments from global (lane<->element map is exact; bias col 28 is a
// compile-time constant). Weights (B operands) stay in swizzled SMEM.
//   h_{t+1} = tanh(x_t@W_ih^T + b + h_t@W_hh^T), t=0..27; out = h@W_fc^T + b_fc
// Grid: 256 CTAs x 64 threads (2 warps of m32n128); CTA = 64 batch rows.
// ============================================================================

#define SM_WHH 0          // 128 x 128 fp16, row stride 256B, swz ^(row&7)
#define SM_WIH 32768      // 128 x 32 fp16, row stride 64B, swz ^(row&3); col28=bias
#define SM_WFC 40960      // 10 x 128 fp32
#define SM_BFC 46080      // 10 fp32
#define SM_TOTAL 46144
// post-loop alias: fp32 h28 at smem offset 0, stride 132 floats (64*132*4=33792)

static __device__ __forceinline__ uint32_t s2u(const void* p) {
    uint32_t a;
    asm("{ .reg .u64 t; cvta.to.shared.u64 t, %1; cvt.u32.u64 %0, t; }"
        : "=r"(a) : "l"(p));
    return a;
}

// pack two floats -> fp16x2, v0 in low half
static __device__ __forceinline__ uint32_t packh(float v0, float v1) {
    uint32_t r;
    asm("cvt.rn.f16x2.f32 %0, %1, %2;" : "=r"(r) : "f"(v1), "f"(v0));
    return r;
}

// load a float2 from global, pack to fp16x2 (v.x in low half)
static __device__ __forceinline__ uint32_t ldpair(const float* p) {
    float2 v = *(const float2*)p;
    return packh(v.x, v.y);
}

// fast tanh: single MUFU op
static __device__ __forceinline__ float tanh_fast(float v) {
    float r;
    asm("tanh.approx.f32 %0, %1;" : "=f"(r) : "f"(v));
    return r;
}

// accurate tanh for the final step
static __device__ __forceinline__ float tanh_acc(float v) {
    float a = fminf(fmaxf(v * 2.885390082f, -30.0f), 30.0f);
    float e; asm("ex2.approx.f32 %0, %1;" : "=f"(e) : "f"(a));
    float r; asm("rcp.approx.f32 %0, %1;" : "=f"(r) : "f"(e + 1.0f));
    return fmaf(-2.0f, r, 1.0f);
}

#define LDSM4(R, A)                                                              \
    asm volatile("ldmatrix.sync.aligned.m8n8.x4.shared.b16 {%0,%1,%2,%3}, [%4];" \
                 : "=r"((R)[0]), "=r"((R)[1]), "=r"((R)[2]), "=r"((R)[3])        \
                 : "r"(A))

static __device__ __forceinline__ void mma_f16(float* d, const uint32_t* a,
                                               uint32_t b0, uint32_t b1) {
    asm volatile(
        "mma.sync.aligned.m16n8k16.row.col.f32.f16.f16.f32 "
        "{%0,%1,%2,%3}, {%4,%5,%6,%7}, {%8,%9}, {%0,%1,%2,%3};"
        : "+f"(d[0]), "+f"(d[1]), "+f"(d[2]), "+f"(d[3])
        : "r"(a[0]), "r"(a[1]), "r"(a[2]), "r"(a[3]), "r"(b0), "r"(b1));
}

__global__ void __launch_bounds__(64) SimpleRNN_fused_kernel(
    const float* __restrict__ x,    // [16384,1,28,28]
    const float* __restrict__ Wih,  // [128,28]
    const float* __restrict__ Whh,  // [128,128]
    const float* __restrict__ bih,  // [128]
    const float* __restrict__ bhh,  // [128]
    const float* __restrict__ Wfc,  // [10,128]
    const float* __restrict__ bfc,  // [10]
    float* __restrict__ out)        // [16384,10]
{
    extern __shared__ char smem[];
    const uint32_t sb = s2u(smem);
    const int tid  = threadIdx.x;        // 0..63
    const int lane = tid & 31;
    const int wid  = tid >> 5;           // warp: rows [wid*32, wid*32+32)
    const int g = lane >> 2;             // accumulator row group 0..7
    const int q = lane & 3;              // accumulator col pair 0..3

    const int rowB = ((lane >> 4) << 3) | (lane & 7);  // B ldmatrix row
    const int csB  = (lane >> 3) & 1;                  // B k-half
    const int l7 = lane & 7, l3 = lane & 3;

    // ---- one-time: weights -> fp16 swizzled SMEM ----
    for (int i = tid; i < 128 * 128; i += 64) {
        int n = i >> 7, k = i & 127;
        uint32_t byte = (uint32_t)(n * 256 + (((k >> 3) ^ (n & 7)) << 4) + (k & 7) * 2);
        *(uint16_t*)(smem + SM_WHH + byte) = __half_as_ushort(__float2half_rn(Whh[i]));
    }
    for (int i = tid; i < 128 * 32; i += 64) {
        int n = i >> 5, k = i & 31;
        float v = (k < 28) ? Wih[n * 28 + k] : ((k == 28) ? (bih[n] + bhh[n]) : 0.0f);
        uint32_t byte = (uint32_t)(n * 64 + (((k >> 3) ^ (n & 3)) << 4) + (k & 7) * 2);
        *(uint16_t*)(smem + SM_WIH + byte) = __half_as_ushort(__float2half_rn(v));
    }
    for (int i = tid; i < 1280; i += 64) ((float*)(smem + SM_WFC))[i] = Wfc[i];
    if (tid < 10) ((float*)(smem + SM_BFC))[tid] = bfc[tid];
    __syncthreads();

    // per-thread x row pointer: global row = blk*64 + wid*32 + (mt*16 + g [+8])
    const float* pg = x + ((size_t)blockIdx.x * 64 + wid * 32 + g) * 784;

    // load x A-fragments for timestep tt into Ax
    #define LOAD_AX(Ax, tt)                                                        \
        do {                                                                       \
            _Pragma("unroll")                                                      \
            for (int mt = 0; mt < 2; mt++) {                                       \
                const float* rlo = pg + (mt * 16) * 784 + (tt) * 28;               \
                const float* rhi = rlo + 8 * 784;                                  \
                _Pragma("unroll")                                                  \
                for (int kt = 0; kt < 2; kt++) {                                   \
                    int c0 = kt * 16 + 2 * q;                                      \
                    (Ax)[mt][kt][0] = ldpair(rlo + c0);                            \
                    (Ax)[mt][kt][1] = ldpair(rhi + c0);                            \
                    if (kt == 0 || q < 2) {                                        \
                        (Ax)[mt][kt][2] = ldpair(rlo + c0 + 8);                    \
                        (Ax)[mt][kt][3] = ldpair(rhi + c0 + 8);                    \
                    } else if (q == 2) {   /* cols 28,29 = (1.0, 0) bias */        \
                        (Ax)[mt][kt][2] = 0x00003C00u;                             \
                        (Ax)[mt][kt][3] = 0x00003C00u;                             \
                    } else {               /* cols 30,31 = 0 */                    \
                        (Ax)[mt][kt][2] = 0u;                                      \
                        (Ax)[mt][kt][3] = 0u;                                      \
                    }                                                              \
                }                                                                  \
            }                                                                      \
        } while (0)

    float acc[8][2][2][4];   // [ng(n16 grp)][mt][n8][4]  (= 128 f32)
    uint32_t Ah[2][8][4];    // packed h A-frags [mt][kc]  (= 64 u32)
    uint32_t Ax[2][2][4];    // x A-frags for current step

    LOAD_AX(Ax, 0);

    #pragma unroll 1
    for (int t = 0; t < 28; t++) {
        #pragma unroll
        for (int ng = 0; ng < 8; ng++)
            #pragma unroll
            for (int mt = 0; mt < 2; mt++)
                #pragma unroll
                for (int nb = 0; nb < 2; nb++)
                    #pragma unroll
                    for (int j = 0; j < 4; j++) acc[ng][mt][nb][j] = 0.0f;

        // ---- x phase: K=32 against W_ih (+bias col) ----
        #pragma unroll
        for (int ng = 0; ng < 8; ng++) {
            uint32_t B0[4], B1[4];
            LDSM4(B0, sb + SM_WIH + (uint32_t)((ng * 16 + rowB) * 64 + ((csB ^ l3) << 4)));
            LDSM4(B1, sb + SM_WIH + (uint32_t)((ng * 16 + rowB) * 64 + (((2 + csB) ^ l3) << 4)));
            #pragma unroll
            for (int mt = 0; mt < 2; mt++) {
                mma_f16(acc[ng][mt][0], Ax[mt][0], B0[0], B0[1]);
                mma_f16(acc[ng][mt][1], Ax[mt][0], B0[2], B0[3]);
                mma_f16(acc[ng][mt][0], Ax[mt][1], B1[0], B1[1]);
                mma_f16(acc[ng][mt][1], Ax[mt][1], B1[2], B1[3]);
            }
        }

        // prefetch next step's x A-fragments (latency hidden under hh phase)
        if (t < 27) LOAD_AX(Ax, t + 1);

        // ---- hh phase: K=128 against W_hh; tanh folded per n16 group ----
        if (t > 0) {
            #pragma unroll
            for (int ng = 0; ng < 8; ng++) {
                #pragma unroll
                for (int kt = 0; kt < 8; kt++) {
                    uint32_t Bh[4];
                    LDSM4(Bh, sb + SM_WHH +
                          (uint32_t)((ng * 16 + rowB) * 256 + (((kt * 2 + csB) ^ l7) << 4)));
                    #pragma unroll
                    for (int mt = 0; mt < 2; mt++) {
                        mma_f16(acc[ng][mt][0], Ah[mt][kt], Bh[0], Bh[1]);
                        mma_f16(acc[ng][mt][1], Ah[mt][kt], Bh[2], Bh[3]);
                    }
                }
                if (t < 27) {
                    #pragma unroll
                    for (int mt = 0; mt < 2; mt++)
                        #pragma unroll
                        for (int nb = 0; nb < 2; nb++)
                            #pragma unroll
                            for (int j = 0; j < 4; j++)
                                acc[ng][mt][nb][j] = tanh_fast(acc[ng][mt][nb][j]);
                }
            }
        } else {
            #pragma unroll
            for (int ng = 0; ng < 8; ng++)
                #pragma unroll
                for (int mt = 0; mt < 2; mt++)
                    #pragma unroll
                    for (int nb = 0; nb < 2; nb++)
                        #pragma unroll
                        for (int j = 0; j < 4; j++)
                            acc[ng][mt][nb][j] = tanh_fast(acc[ng][mt][nb][j]);
        }

        if (t < 27) {
            // ---- pack C-fragment -> A-fragment (layout identity, no shuffle) ----
            #pragma unroll
            for (int mt = 0; mt < 2; mt++)
                #pragma unroll
                for (int kc = 0; kc < 8; kc++) {
                    Ah[mt][kc][0] = packh(acc[kc][mt][0][0], acc[kc][mt][0][1]);
                    Ah[mt][kc][1] = packh(acc[kc][mt][0][2], acc[kc][mt][0][3]);
                    Ah[mt][kc][2] = packh(acc[kc][mt][1][0], acc[kc][mt][1][1]);
                    Ah[mt][kc][3] = packh(acc[kc][mt][1][2], acc[kc][mt][1][3]);
                }
        }
    }

    // ---- final: h28 (accurate tanh) -> smem fp32, then SIMT fc ----
    __syncthreads();  // both warps done with W_hh before aliasing over it
    {
        float* h32 = (float*)smem;
        #pragma unroll
        for (int ng = 0; ng < 8; ng++)
            #pragma unroll
            for (int mt = 0; mt < 2; mt++)
                #pragma unroll
                for (int nb = 0; nb < 2; nb++) {
                    const float* c = acc[ng][mt][nb];
                    int r = wid * 32 + mt * 16 + g;
                    int col = ng * 16 + nb * 8 + 2 * q;
                    *(float2*)(h32 + r * 132 + col) =
                        make_float2(tanh_acc(c[0]), tanh_acc(c[1]));
                    *(float2*)(h32 + (r + 8) * 132 + col) =
                        make_float2(tanh_acc(c[2]), tanh_acc(c[3]));
                }
    }
    __syncthreads();

    {
        const float* h32  = (const float*)smem;
        const float* wfc  = (const float*)(smem + SM_WFC);
        const float* bfcS = (const float*)(smem + SM_BFC);
        int r = tid;  // one batch row per thread (64 rows)
        float s[10];
        #pragma unroll
        for (int j = 0; j < 10; j++) s[j] = bfcS[j];
        const float4* hr = (const float4*)(h32 + r * 132);
        #pragma unroll 4
        for (int k4 = 0; k4 < 32; k4++) {
            float4 hv = hr[k4];
            #pragma unroll
            for (int j = 0; j < 10; j++) {
                float4 wv = ((const float4*)(wfc + j * 128))[k4];
                s[j] += hv.x * wv.x + hv.y * wv.y + hv.z * wv.z + hv.w * wv.w;
            }
        }
        float* o = out + ((size_t)blockIdx.x * 64 + r) * 10;
        #pragma unroll
        for (int j = 0; j < 10; j++) o[j] = s[j];
    }
}

extern "C" void kernel_launch(void* const* d_in, const int* in_sizes, int n_in,
                              void* d_out, int out_size) {
    const float* x   = (const float*)d_in[0];
    const float* Wih = (const float*)d_in[1];
    const float* Whh = (const float*)d_in[2];
    const float* bih = (const float*)d_in[3];
    const float* bhh = (const float*)d_in[4];
    const float* Wfc = (const float*)d_in[5];
    const float* bfc = (const float*)d_in[6];
    float* out = (float*)d_out;

    cudaFuncSetAttribute(SimpleRNN_fused_kernel,
                         cudaFuncAttributeMaxDynamicSharedMemorySize, SM_TOTAL);
    SimpleRNN_fused_kernel<<<256, 64, SM_TOTAL>>>(x, Wih, Whh, bih, bhh, Wfc, bfc, out);
}

// round 9
// speedup vs baseline: 1.2604x; 1.2604x over previous
#include <cuda_runtime.h>
#include <cuda_fp16.h>
#include <cstdint>

// ============================================================================
// SimpleRNN fused kernel R9: register-resident recurrence, m16 x n128/warp.
// The tanh'd C-fragment is repacked in-register as the A-fragment of the next
// step's hh GEMM (C->A layout identity for m16n8k16, verified in R8).
// No barriers in the loop, no h SMEM round-trip. x loads go straight to
// A-fragments from global. Weights (B) in swizzled SMEM.
//   h_{t+1} = tanh(x_t@W_ih^T + b + h_t@W_hh^T), t=0..27; out = h@W_fc^T + b_fc
// Grid: 256 CTAs x 128 threads (4 warps of m16n128); CTA = 64 batch rows.
// ============================================================================

#define SM_WHH 0          // 128 x 128 fp16, row stride 256B, swz ^(row&7)
#define SM_WIH 32768      // 128 x 32 fp16, row stride 64B, swz ^(row&3); col28=bias
#define SM_WFC 40960      // 10 x 128 fp32
#define SM_BFC 46080      // 10 fp32
#define SM_TOTAL 46144
// post-loop alias: fp32 h28 at smem offset 0, stride 132 floats (64*132*4=33792)

static __device__ __forceinline__ uint32_t s2u(const void* p) {
    uint32_t a;
    asm("{ .reg .u64 t; cvta.to.shared.u64 t, %1; cvt.u32.u64 %0, t; }"
        : "=r"(a) : "l"(p));
    return a;
}

// pack two floats -> fp16x2, v0 in low half
static __device__ __forceinline__ uint32_t packh(float v0, float v1) {
    uint32_t r;
    asm("cvt.rn.f16x2.f32 %0, %1, %2;" : "=r"(r) : "f"(v1), "f"(v0));
    return r;
}

// load float2 from global, pack to fp16x2 (v.x in low half)
static __device__ __forceinline__ uint32_t ldpair(const float* p) {
    float2 v = *(const float2*)p;
    return packh(v.x, v.y);
}

// fast tanh: single MUFU op
static __device__ __forceinline__ float tanh_fast(float v) {
    float r;
    asm("tanh.approx.f32 %0, %1;" : "=f"(r) : "f"(v));
    return r;
}

// accurate tanh for the final step
static __device__ __forceinline__ float tanh_acc(float v) {
    float a = fminf(fmaxf(v * 2.885390082f, -30.0f), 30.0f);
    float e; asm("ex2.approx.f32 %0, %1;" : "=f"(e) : "f"(a));
    float r; asm("rcp.approx.f32 %0, %1;" : "=f"(r) : "f"(e + 1.0f));
    return fmaf(-2.0f, r, 1.0f);
}

#define LDSM4(R, A)                                                              \
    asm volatile("ldmatrix.sync.aligned.m8n8.x4.shared.b16 {%0,%1,%2,%3}, [%4];" \
                 : "=r"((R)[0]), "=r"((R)[1]), "=r"((R)[2]), "=r"((R)[3])        \
                 : "r"(A))

static __device__ __forceinline__ void mma_f16(float* d, const uint32_t* a,
                                               uint32_t b0, uint32_t b1) {
    asm volatile(
        "mma.sync.aligned.m16n8k16.row.col.f32.f16.f16.f32 "
        "{%0,%1,%2,%3}, {%4,%5,%6,%7}, {%8,%9}, {%0,%1,%2,%3};"
        : "+f"(d[0]), "+f"(d[1]), "+f"(d[2]), "+f"(d[3])
        : "r"(a[0]), "r"(a[1]), "r"(a[2]), "r"(a[3]), "r"(b0), "r"(b1));
}

__global__ void __launch_bounds__(128, 2) SimpleRNN_fused_kernel(
    const float* __restrict__ x,    // [16384,1,28,28]
    const float* __restrict__ Wih,  // [128,28]
    const float* __restrict__ Whh,  // [128,128]
    const float* __restrict__ bih,  // [128]
    const float* __restrict__ bhh,  // [128]
    const float* __restrict__ Wfc,  // [10,128]
    const float* __restrict__ bfc,  // [10]
    float* __restrict__ out)        // [16384,10]
{
    extern __shared__ char smem[];
    const uint32_t sb = s2u(smem);
    const int tid  = threadIdx.x;        // 0..127
    const int lane = tid & 31;
    const int wid  = tid >> 5;           // warp: rows [wid*16, wid*16+16)
    const int g = lane >> 2;             // accumulator row 0..7 (and +8)
    const int q = lane & 3;              // accumulator col pair 0..3

    const int rowB = ((lane >> 4) << 3) | (lane & 7);  // B ldmatrix row
    const int csB  = (lane >> 3) & 1;                  // B k-half
    const int l7 = lane & 7, l3 = lane & 3;

    // ---- one-time: weights -> fp16 swizzled SMEM ----
    for (int i = tid; i < 128 * 128; i += 128) {
        int n = i >> 7, k = i & 127;
        uint32_t byte = (uint32_t)(n * 256 + (((k >> 3) ^ (n & 7)) << 4) + (k & 7) * 2);
        *(uint16_t*)(smem + SM_WHH + byte) = __half_as_ushort(__float2half_rn(Whh[i]));
    }
    for (int i = tid; i < 128 * 32; i += 128) {
        int n = i >> 5, k = i & 31;
        float v = (k < 28) ? Wih[n * 28 + k] : ((k == 28) ? (bih[n] + bhh[n]) : 0.0f);
        uint32_t byte = (uint32_t)(n * 64 + (((k >> 3) ^ (n & 3)) << 4) + (k & 7) * 2);
        *(uint16_t*)(smem + SM_WIH + byte) = __half_as_ushort(__float2half_rn(v));
    }
    for (int i = tid; i < 1280; i += 128) ((float*)(smem + SM_WFC))[i] = Wfc[i];
    if (tid < 10) ((float*)(smem + SM_BFC))[tid] = bfc[tid];
    __syncthreads();

    // per-thread x row pointers: rows g and g+8 of this warp's 16-row block
    const float* plo = x + ((size_t)blockIdx.x * 64 + wid * 16 + g) * 784;
    const float* phi = plo + 8 * 784;

    // A-fragment layout (m16n8k16, row-major A):
    //   reg0 = (g, kc*16+2q, +1), reg1 = (g+8, same), reg2 = (g, kc*16+8+2q, +1),
    //   reg3 = (g+8, same)
    #define LOAD_AX(Ax, tt)                                                        \
        do {                                                                       \
            const float* rl = plo + (tt) * 28;                                     \
            const float* rh = phi + (tt) * 28;                                     \
            _Pragma("unroll")                                                      \
            for (int kt = 0; kt < 2; kt++) {                                       \
                int c0 = kt * 16 + 2 * q;                                          \
                (Ax)[kt][0] = ldpair(rl + c0);                                     \
                (Ax)[kt][1] = ldpair(rh + c0);                                     \
                if (kt == 0 || q < 2) {                                            \
                    (Ax)[kt][2] = ldpair(rl + c0 + 8);                             \
                    (Ax)[kt][3] = ldpair(rh + c0 + 8);                             \
                } else if (q == 2) {   /* cols 28,29 = (1.0, 0) bias */            \
                    (Ax)[kt][2] = 0x00003C00u;                                     \
                    (Ax)[kt][3] = 0x00003C00u;                                     \
                } else {               /* cols 30,31 = 0 */                        \
                    (Ax)[kt][2] = 0u;                                              \
                    (Ax)[kt][3] = 0u;                                              \
                }                                                                  \
            }                                                                      \
        } while (0)

    float acc[8][2][4];   // [ng(n16 grp)][n8][4]  = 64 f32
    uint32_t Ah[8][4];    // packed h A-frags per k16 chunk = 32 u32
    uint32_t Ax[2][4];    // x A-frags

    LOAD_AX(Ax, 0);

    #pragma unroll 1
    for (int t = 0; t < 28; t++) {
        #pragma unroll
        for (int ng = 0; ng < 8; ng++)
            #pragma unroll
            for (int nb = 0; nb < 2; nb++)
                #pragma unroll
                for (int j = 0; j < 4; j++) acc[ng][nb][j] = 0.0f;

        // ---- x phase: K=32 against W_ih (+bias col) ----
        #pragma unroll
        for (int ng = 0; ng < 8; ng++) {
            uint32_t B0[4], B1[4];
            LDSM4(B0, sb + SM_WIH + (uint32_t)((ng * 16 + rowB) * 64 + ((csB ^ l3) << 4)));
            LDSM4(B1, sb + SM_WIH + (uint32_t)((ng * 16 + rowB) * 64 + (((2 + csB) ^ l3) << 4)));
            mma_f16(acc[ng][0], Ax[0], B0[0], B0[1]);
            mma_f16(acc[ng][1], Ax[0], B0[2], B0[3]);
            mma_f16(acc[ng][0], Ax[1], B1[0], B1[1]);
            mma_f16(acc[ng][1], Ax[1], B1[2], B1[3]);
        }

        // prefetch next step's x A-fragments (hidden under hh phase)
        if (t < 27) LOAD_AX(Ax, t + 1);

        // ---- hh phase: K=128 against W_hh; tanh folded per n16 group ----
        if (t > 0) {
            #pragma unroll
            for (int ng = 0; ng < 8; ng++) {
                #pragma unroll
                for (int kt = 0; kt < 8; kt++) {
                    uint32_t Bh[4];
                    LDSM4(Bh, sb + SM_WHH +
                          (uint32_t)((ng * 16 + rowB) * 256 + (((kt * 2 + csB) ^ l7) << 4)));
                    mma_f16(acc[ng][0], Ah[kt], Bh[0], Bh[1]);
                    mma_f16(acc[ng][1], Ah[kt], Bh[2], Bh[3]);
                }
                if (t < 27) {
                    #pragma unroll
                    for (int nb = 0; nb < 2; nb++)
                        #pragma unroll
                        for (int j = 0; j < 4; j++)
                            acc[ng][nb][j] = tanh_fast(acc[ng][nb][j]);
                }
            }
        } else {
            #pragma unroll
            for (int ng = 0; ng < 8; ng++)
                #pragma unroll
                for (int nb = 0; nb < 2; nb++)
                    #pragma unroll
                    for (int j = 0; j < 4; j++)
                        acc[ng][nb][j] = tanh_fast(acc[ng][nb][j]);
        }

        if (t < 27) {
            // ---- pack C-fragment -> A-fragment (layout identity) ----
            #pragma unroll
            for (int kc = 0; kc < 8; kc++) {
                Ah[kc][0] = packh(acc[kc][0][0], acc[kc][0][1]);  // (g,   kc*16+2q)
                Ah[kc][1] = packh(acc[kc][0][2], acc[kc][0][3]);  // (g+8, kc*16+2q)
                Ah[kc][2] = packh(acc[kc][1][0], acc[kc][1][1]);  // (g,   kc*16+8+2q)
                Ah[kc][3] = packh(acc[kc][1][2], acc[kc][1][3]);  // (g+8, kc*16+8+2q)
            }
        }
    }

    // ---- final: h28 (accurate tanh) -> smem fp32, then SIMT fc ----
    __syncthreads();  // all warps done with W_hh before aliasing over it
    {
        float* h32 = (float*)smem;
        #pragma unroll
        for (int ng = 0; ng < 8; ng++)
            #pragma unroll
            for (int nb = 0; nb < 2; nb++) {
                const float* c = acc[ng][nb];
                int r = wid * 16 + g;
                int col = ng * 16 + nb * 8 + 2 * q;
                *(float2*)(h32 + r * 132 + col) =
                    make_float2(tanh_acc(c[0]), tanh_acc(c[1]));
                *(float2*)(h32 + (r + 8) * 132 + col) =
                    make_float2(tanh_acc(c[2]), tanh_acc(c[3]));
            }
    }
    __syncthreads();

    // fc: out = h28 @ W_fc^T + b_fc (fp32 SIMT; 128 threads, 64 rows x 2 halves)
    {
        const float* h32  = (const float*)smem;
        const float* wfc  = (const float*)(smem + SM_WFC);
        const float* bfcS = (const float*)(smem + SM_BFC);
        int r = tid >> 1;
        int c0 = (tid & 1) * 5;
        float s[5];
        #pragma unroll
        for (int j = 0; j < 5; j++) s[j] = bfcS[c0 + j];
        const float4* hr = (const float4*)(h32 + r * 132);
        #pragma unroll 8
        for (int k4 = 0; k4 < 32; k4++) {
            float4 hv = hr[k4];
            #pragma unroll
            for (int j = 0; j < 5; j++) {
                float4 wv = ((const float4*)(wfc + (c0 + j) * 128))[k4];
                s[j] += hv.x * wv.x + hv.y * wv.y + hv.z * wv.z + hv.w * wv.w;
            }
        }
        float* o = out + ((size_t)blockIdx.x * 64 + r) * 10 + c0;
        #pragma unroll
        for (int j = 0; j < 5; j++) o[j] = s[j];
    }
}

extern "C" void kernel_launch(void* const* d_in, const int* in_sizes, int n_in,
                              void* d_out, int out_size) {
    const float* x   = (const float*)d_in[0];
    const float* Wih = (const float*)d_in[1];
    const float* Whh = (const float*)d_in[2];
    const float* bih = (const float*)d_in[3];
    const float* bhh = (const float*)d_in[4];
    const float* Wfc = (const float*)d_in[5];
    const float* bfc = (const float*)d_in[6];
    float* out = (float*)d_out;

    cudaFuncSetAttribute(SimpleRNN_fused_kernel,
                         cudaFuncAttributeMaxDynamicSharedMemorySize, SM_TOTAL);
    SimpleRNN_fused_kernel<<<256, 128, SM_TOTAL>>>(x, Wih, Whh, bih, bhh, Wfc, bfc, out);
}

// round 10
// speedup vs baseline: 1.3194x; 1.0468x over previous
#include <cuda_runtime.h>
#include <cuda_fp16.h>
#include <cstdint>

// ============================================================================
// SimpleRNN fused kernel R10 = R7 base (16 warps/SM, smem-h ping-pong) +
//  (a) ALL weight B-fragments cached in registers (zero B-LDSM in the loop)
//  (b) x A-fragments loaded directly from global (no x SMEM staging)
//   h_{t+1} = tanh(x_t@W_ih^T + b + h_t@W_hh^T), t=0..27; out = h@W_fc^T + b_fc
// Grid: 256 CTAs x 256 threads (8 warps, m32n32 tiles, 2m x 4n); CTA = 64 rows.
// ============================================================================

#define SM_WHH 0          // 128 x 128 fp16, row stride 256B, swz ^(row&7)
#define SM_WIH 32768      // 128 x 32 fp16, row stride 64B, swz ^(row&3); col28=bias
#define SM_H0  40960      // 64 x 128 fp16 ping
#define SM_H1  57344      // pong
#define SM_WFC 73728      // 10 x 128 fp32
#define SM_BFC 78848      // 10 fp32
#define SM_TOTAL 78912
// post-loop alias: fp32 h28 at smem offset 0, stride 132 floats

static __device__ __forceinline__ uint32_t s2u(const void* p) {
    uint32_t a;
    asm("{ .reg .u64 t; cvta.to.shared.u64 t, %1; cvt.u32.u64 %0, t; }"
        : "=r"(a) : "l"(p));
    return a;
}

// pack two floats -> fp16x2, v0 in low half
static __device__ __forceinline__ uint32_t packh(float v0, float v1) {
    uint32_t r;
    asm("cvt.rn.f16x2.f32 %0, %1, %2;" : "=r"(r) : "f"(v1), "f"(v0));
    return r;
}

// load float2 from global, pack to fp16x2 (v.x in low half)
static __device__ __forceinline__ uint32_t ldpair(const float* p) {
    float2 v = *(const float2*)p;
    return packh(v.x, v.y);
}

// fast tanh: single MUFU op
static __device__ __forceinline__ float tanh_fast(float v) {
    float r;
    asm("tanh.approx.f32 %0, %1;" : "=f"(r) : "f"(v));
    return r;
}

// accurate tanh for the final step
static __device__ __forceinline__ float tanh_acc(float v) {
    float a = fminf(fmaxf(v * 2.885390082f, -30.0f), 30.0f);
    float e; asm("ex2.approx.f32 %0, %1;" : "=f"(e) : "f"(a));
    float r; asm("rcp.approx.f32 %0, %1;" : "=f"(r) : "f"(e + 1.0f));
    return fmaf(-2.0f, r, 1.0f);
}

#define LDSM4(R, A)                                                              \
    asm volatile("ldmatrix.sync.aligned.m8n8.x4.shared.b16 {%0,%1,%2,%3}, [%4];" \
                 : "=r"((R)[0]), "=r"((R)[1]), "=r"((R)[2]), "=r"((R)[3])        \
                 : "r"(A))

static __device__ __forceinline__ void mma_f16(float* d, const uint32_t* a,
                                               uint32_t b0, uint32_t b1) {
    asm volatile(
        "mma.sync.aligned.m16n8k16.row.col.f32.f16.f16.f32 "
        "{%0,%1,%2,%3}, {%4,%5,%6,%7}, {%8,%9}, {%0,%1,%2,%3};"
        : "+f"(d[0]), "+f"(d[1]), "+f"(d[2]), "+f"(d[3])
        : "r"(a[0]), "r"(a[1]), "r"(a[2]), "r"(a[3]), "r"(b0), "r"(b1));
}

__global__ void __launch_bounds__(256, 2) SimpleRNN_fused_kernel(
    const float* __restrict__ x,    // [16384,1,28,28]
    const float* __restrict__ Wih,  // [128,28]
    const float* __restrict__ Whh,  // [128,128]
    const float* __restrict__ bih,  // [128]
    const float* __restrict__ bhh,  // [128]
    const float* __restrict__ Wfc,  // [10,128]
    const float* __restrict__ bfc,  // [10]
    float* __restrict__ out)        // [16384,10]
{
    extern __shared__ char smem[];
    const uint32_t sb = s2u(smem);
    const int tid  = threadIdx.x;
    const int lane = tid & 31;
    const int wid  = tid >> 5;
    const int m0 = (wid & 1) * 32;   // warp M offset
    const int n0 = (wid >> 1) * 32;  // warp N offset
    const int g = lane >> 2;         // A/C row within 8-group
    const int q = lane & 3;          // A/C col pair

    const int rowA = lane & 15;
    const int csA  = lane >> 4;
    const int rowB = ((lane >> 4) << 3) | (lane & 7);
    const int csB  = (lane >> 3) & 1;
    const int l7 = lane & 7, l3 = lane & 3;

    // ---- one-time: weights -> fp16 swizzled SMEM ----
    for (int i = tid; i < 128 * 128; i += 256) {
        int n = i >> 7, k = i & 127;
        uint32_t byte = (uint32_t)(n * 256 + (((k >> 3) ^ (n & 7)) << 4) + (k & 7) * 2);
        *(uint16_t*)(smem + SM_WHH + byte) = __half_as_ushort(__float2half_rn(Whh[i]));
    }
    for (int i = tid; i < 128 * 32; i += 256) {
        int n = i >> 5, k = i & 31;
        float v = (k < 28) ? Wih[n * 28 + k] : ((k == 28) ? (bih[n] + bhh[n]) : 0.0f);
        uint32_t byte = (uint32_t)(n * 64 + (((k >> 3) ^ (n & 3)) << 4) + (k & 7) * 2);
        *(uint16_t*)(smem + SM_WIH + byte) = __half_as_ushort(__float2half_rn(v));
    }
    for (int i = tid; i < 1280; i += 256) ((float*)(smem + SM_WFC))[i] = Wfc[i];
    if (tid < 10) ((float*)(smem + SM_BFC))[tid] = bfc[tid];
    __syncthreads();

    // ---- cache ALL B fragments in registers (weights are constant) ----
    uint32_t Bih[2][2][4];  // [kt][nt]
    #pragma unroll
    for (int kt = 0; kt < 2; kt++)
        #pragma unroll
        for (int nt = 0; nt < 2; nt++)
            LDSM4(Bih[kt][nt], sb + SM_WIH +
                  (uint32_t)((n0 + nt * 16 + rowB) * 64 + (((kt * 2 + csB) ^ l3) << 4)));
    uint32_t Bhh[8][2][4];  // [kt][nt]
    #pragma unroll
    for (int kt = 0; kt < 8; kt++)
        #pragma unroll
        for (int nt = 0; nt < 2; nt++)
            LDSM4(Bhh[kt][nt], sb + SM_WHH +
                  (uint32_t)((n0 + nt * 16 + rowB) * 256 + (((kt * 2 + csB) ^ l7) << 4)));

    // ---- x direct-from-global A-fragments ----
    // rows for this warp: m0 + mt*16 + g and +8
    const float* pr[2][2];  // [mt][lo/hi]
    #pragma unroll
    for (int mt = 0; mt < 2; mt++) {
        pr[mt][0] = x + ((size_t)blockIdx.x * 64 + m0 + mt * 16 + g) * 784;
        pr[mt][1] = pr[mt][0] + 8 * 784;
    }

    #define LOAD_AX(Ax, tt)                                                        \
        do {                                                                       \
            _Pragma("unroll")                                                      \
            for (int mt = 0; mt < 2; mt++) {                                       \
                const float* rl = pr[mt][0] + (tt) * 28;                           \
                const float* rh = pr[mt][1] + (tt) * 28;                           \
                _Pragma("unroll")                                                  \
                for (int kt = 0; kt < 2; kt++) {                                   \
                    int c0 = kt * 16 + 2 * q;                                      \
                    (Ax)[mt][kt][0] = ldpair(rl + c0);                             \
                    (Ax)[mt][kt][1] = ldpair(rh + c0);                             \
                    if (kt == 0 || q < 2) {                                        \
                        (Ax)[mt][kt][2] = ldpair(rl + c0 + 8);                     \
                        (Ax)[mt][kt][3] = ldpair(rh + c0 + 8);                     \
                    } else if (q == 2) {   /* cols 28,29 = (1.0, 0) bias */        \
                        (Ax)[mt][kt][2] = 0x00003C00u;                             \
                        (Ax)[mt][kt][3] = 0x00003C00u;                             \
                    } else {                                                       \
                        (Ax)[mt][kt][2] = 0u;                                      \
                        (Ax)[mt][kt][3] = 0u;                                      \
                    }                                                              \
                }                                                                  \
            }                                                                      \
        } while (0)

    float acc[2][4][4];     // [mt][n8][4]
    uint32_t Ax[2][2][4];   // [mt][kt]

    LOAD_AX(Ax, 0);

    #pragma unroll 1
    for (int t = 0; t < 28; t++) {
        const uint32_t Hrd = (t & 1) ? SM_H1 : SM_H0;
        const uint32_t Hwr = (t & 1) ? SM_H0 : SM_H1;

        #pragma unroll
        for (int mt = 0; mt < 2; mt++)
            #pragma unroll
            for (int nt = 0; nt < 4; nt++)
                #pragma unroll
                for (int j = 0; j < 4; j++) acc[mt][nt][j] = 0.0f;

        // ---- x GEMM (K=32): A from registers, B cached ----
        #pragma unroll
        for (int kt = 0; kt < 2; kt++)
            #pragma unroll
            for (int mt = 0; mt < 2; mt++)
                #pragma unroll
                for (int nt = 0; nt < 2; nt++) {
                    mma_f16(acc[mt][2*nt],   Ax[mt][kt], Bih[kt][nt][0], Bih[kt][nt][1]);
                    mma_f16(acc[mt][2*nt+1], Ax[mt][kt], Bih[kt][nt][2], Bih[kt][nt][3]);
                }

        // ---- hh GEMM (K=128): A from smem LDSM, B cached ----
        if (t > 0) {
            #pragma unroll
            for (int kt = 0; kt < 8; kt++) {
                uint32_t A[2][4];
                #pragma unroll
                for (int mt = 0; mt < 2; mt++)
                    LDSM4(A[mt], sb + Hrd +
                          (uint32_t)((m0 + mt * 16 + rowA) * 256 + (((kt * 2 + csA) ^ l7) << 4)));
                #pragma unroll
                for (int mt = 0; mt < 2; mt++)
                    #pragma unroll
                    for (int nt = 0; nt < 2; nt++) {
                        mma_f16(acc[mt][2*nt],   A[mt], Bhh[kt][nt][0], Bhh[kt][nt][1]);
                        mma_f16(acc[mt][2*nt+1], A[mt], Bhh[kt][nt][2], Bhh[kt][nt][3]);
                    }
            }
        }

        // prefetch x(t+1) A-fragments (overlaps with epilogue below)
        if (t < 27) LOAD_AX(Ax, t + 1);

        if (t < 27) {
            // h(t+1) = tanh.approx(acc) -> fp16 into Hwr ping-pong
            #pragma unroll
            for (int mt = 0; mt < 2; mt++)
                #pragma unroll
                for (int nt = 0; nt < 4; nt++) {
                    const float* c = acc[mt][nt];
                    int r0 = m0 + mt * 16 + g;
                    int r1 = r0 + 8;
                    int chunk = (n0 >> 3) + nt;
                    uint32_t b0 = (uint32_t)(r0 * 256 + ((chunk ^ (r0 & 7)) << 4) + q * 4);
                    uint32_t b1 = (uint32_t)(r1 * 256 + ((chunk ^ (r1 & 7)) << 4) + q * 4);
                    *(uint32_t*)(smem + Hwr + b0) = packh(tanh_fast(c[0]), tanh_fast(c[1]));
                    *(uint32_t*)(smem + Hwr + b1) = packh(tanh_fast(c[2]), tanh_fast(c[3]));
                }
        } else {
            // final step: accurate tanh, fp32 h28 over dead W_hh; barrier first
            __syncthreads();
            float* h32 = (float*)smem;
            #pragma unroll
            for (int mt = 0; mt < 2; mt++)
                #pragma unroll
                for (int nt = 0; nt < 4; nt++) {
                    const float* c = acc[mt][nt];
                    int r0 = m0 + mt * 16 + g;
                    int col = n0 + nt * 8 + 2 * q;
                    *(float2*)(h32 + r0 * 132 + col)       = make_float2(tanh_acc(c[0]), tanh_acc(c[1]));
                    *(float2*)(h32 + (r0 + 8) * 132 + col) = make_float2(tanh_acc(c[2]), tanh_acc(c[3]));
                }
        }
        __syncthreads();
    }

    // ---- fc: out = h28 @ W_fc^T + b_fc (fp32 SIMT, 128 threads) ----
    if (tid < 128) {
        const float* h32  = (const float*)smem;
        const float* wfc  = (const float*)(smem + SM_WFC);
        const float* bfcS = (const float*)(smem + SM_BFC);
        int r = tid >> 1;
        int c0 = (tid & 1) * 5;
        float s[5];
        #pragma unroll
        for (int j = 0; j < 5; j++) s[j] = bfcS[c0 + j];
        const float4* hr = (const float4*)(h32 + r * 132);
        #pragma unroll 8
        for (int k4 = 0; k4 < 32; k4++) {
            float4 hv = hr[k4];
            #pragma unroll
            for (int j = 0; j < 5; j++) {
                float4 wv = ((const float4*)(wfc + (c0 + j) * 128))[k4];
                s[j] += hv.x * wv.x + hv.y * wv.y + hv.z * wv.z + hv.w * wv.w;
            }
        }
        float* o = out + ((size_t)blockIdx.x * 64 + r) * 10 + c0;
        #pragma unroll
        for (int j = 0; j < 5; j++) o[j] = s[j];
    }
}

extern "C" void kernel_launch(void* const* d_in, const int* in_sizes, int n_in,
                              void* d_out, int out_size) {
    const float* x   = (const float*)d_in[0];
    const float* Wih = (const float*)d_in[1];
    const float* Whh = (const float*)d_in[2];
    const float* bih = (const float*)d_in[3];
    const float* bhh = (const float*)d_in[4];
    const float* Wfc = (const float*)d_in[5];
    const float* bfc = (const float*)d_in[6];
    float* out = (float*)d_out;

    cudaFuncSetAttribute(SimpleRNN_fused_kernel,
                         cudaFuncAttributeMaxDynamicSharedMemorySize, SM_TOTAL);
    SimpleRNN_fused_kernel<<<256, 256, SM_TOTAL>>>(x, Wih, Whh, bih, bhh, Wfc, bfc, out);
}

// round 11
// speedup vs baseline: 1.5955x; 1.2093x over previous
#include <cuda_runtime.h>
#include <cuda_fp16.h>
#include <cstdint>

// ============================================================================
// SimpleRNN fused kernel R11: big-tile low-occupancy variant.
// 256 threads/SM (CTA=128thr x 2 CTAs/SM) -> 256-reg budget. Warp tile m32xn64.
// Register-cached: Bih (all), Bhh (kt 0..3 of 8). LDSM per warp/step: A 16 +
// Bhh-tail 16 = 32 x4-ops (vs R7's 36 across 2x the warps) -> L1 busy ~14us,
// under the ~29us HMMA floor measured constant across R4-R10.
//   h_{t+1} = tanh(x_t@W_ih^T + b + h_t@W_hh^T), t=0..27; out = h@W_fc^T + b_fc
// Grid: 256 CTAs x 128 threads; CTA = 64 batch rows; warps 2m x 2n.
// ============================================================================

#define SM_WHH 0          // 128 x 128 fp16, row stride 256B, swz ^(row&7)
#define SM_WIH 32768      // 128 x 32 fp16, row stride 64B, swz ^(row&3); col28=bias
#define SM_H0  40960      // 64 x 128 fp16 ping
#define SM_H1  57344      // pong
#define SM_WFC 73728      // 10 x 128 fp32
#define SM_BFC 78848      // 10 fp32
#define SM_TOTAL 78912
// post-loop alias: fp32 h28 at smem offset 0, stride 132 floats (33792B)

static __device__ __forceinline__ uint32_t s2u(const void* p) {
    uint32_t a;
    asm("{ .reg .u64 t; cvta.to.shared.u64 t, %1; cvt.u32.u64 %0, t; }"
        : "=r"(a) : "l"(p));
    return a;
}

// pack two floats -> fp16x2, v0 in low half
static __device__ __forceinline__ uint32_t packh(float v0, float v1) {
    uint32_t r;
    asm("cvt.rn.f16x2.f32 %0, %1, %2;" : "=r"(r) : "f"(v1), "f"(v0));
    return r;
}

// load float2 from global, pack to fp16x2 (v.x in low half)
static __device__ __forceinline__ uint32_t ldpair(const float* p) {
    float2 v = *(const float2*)p;
    return packh(v.x, v.y);
}

// fast tanh: single MUFU op
static __device__ __forceinline__ float tanh_fast(float v) {
    float r;
    asm("tanh.approx.f32 %0, %1;" : "=f"(r) : "f"(v));
    return r;
}

// accurate tanh for the final step
static __device__ __forceinline__ float tanh_acc(float v) {
    float a = fminf(fmaxf(v * 2.885390082f, -30.0f), 30.0f);
    float e; asm("ex2.approx.f32 %0, %1;" : "=f"(e) : "f"(a));
    float r; asm("rcp.approx.f32 %0, %1;" : "=f"(r) : "f"(e + 1.0f));
    return fmaf(-2.0f, r, 1.0f);
}

#define LDSM4(R, A)                                                              \
    asm volatile("ldmatrix.sync.aligned.m8n8.x4.shared.b16 {%0,%1,%2,%3}, [%4];" \
                 : "=r"((R)[0]), "=r"((R)[1]), "=r"((R)[2]), "=r"((R)[3])        \
                 : "r"(A))

static __device__ __forceinline__ void mma_f16(float* d, const uint32_t* a,
                                               uint32_t b0, uint32_t b1) {
    asm volatile(
        "mma.sync.aligned.m16n8k16.row.col.f32.f16.f16.f32 "
        "{%0,%1,%2,%3}, {%4,%5,%6,%7}, {%8,%9}, {%0,%1,%2,%3};"
        : "+f"(d[0]), "+f"(d[1]), "+f"(d[2]), "+f"(d[3])
        : "r"(a[0]), "r"(a[1]), "r"(a[2]), "r"(a[3]), "r"(b0), "r"(b1));
}

__global__ void __launch_bounds__(128, 2) SimpleRNN_fused_kernel(
    const float* __restrict__ x,    // [16384,1,28,28]
    const float* __restrict__ Wih,  // [128,28]
    const float* __restrict__ Whh,  // [128,128]
    const float* __restrict__ bih,  // [128]
    const float* __restrict__ bhh,  // [128]
    const float* __restrict__ Wfc,  // [10,128]
    const float* __restrict__ bfc,  // [10]
    float* __restrict__ out)        // [16384,10]
{
    extern __shared__ char smem[];
    const uint32_t sb = s2u(smem);
    const int tid  = threadIdx.x;        // 0..127
    const int lane = tid & 31;
    const int wid  = tid >> 5;           // 0..3
    const int m0 = (wid & 1) * 32;       // warp M offset
    const int n0 = (wid >> 1) * 64;      // warp N offset
    const int g = lane >> 2;             // C row in 8-group
    const int q = lane & 3;              // C col pair

    const int rowA = lane & 15;
    const int csA  = lane >> 4;
    const int rowB = ((lane >> 4) << 3) | (lane & 7);
    const int csB  = (lane >> 3) & 1;
    const int l7 = lane & 7, l3 = lane & 3;

    // ---- one-time: weights -> fp16 swizzled SMEM ----
    for (int i = tid; i < 128 * 128; i += 128) {
        int n = i >> 7, k = i & 127;
        uint32_t byte = (uint32_t)(n * 256 + (((k >> 3) ^ (n & 7)) << 4) + (k & 7) * 2);
        *(uint16_t*)(smem + SM_WHH + byte) = __half_as_ushort(__float2half_rn(Whh[i]));
    }
    for (int i = tid; i < 128 * 32; i += 128) {
        int n = i >> 5, k = i & 31;
        float v = (k < 28) ? Wih[n * 28 + k] : ((k == 28) ? (bih[n] + bhh[n]) : 0.0f);
        uint32_t byte = (uint32_t)(n * 64 + (((k >> 3) ^ (n & 3)) << 4) + (k & 7) * 2);
        *(uint16_t*)(smem + SM_WIH + byte) = __half_as_ushort(__float2half_rn(v));
    }
    for (int i = tid; i < 1280; i += 128) ((float*)(smem + SM_WFC))[i] = Wfc[i];
    if (tid < 10) ((float*)(smem + SM_BFC))[tid] = bfc[tid];
    __syncthreads();

    // ---- register caches: Bih all (kt 0,1), Bhh first half (kt 0..3) ----
    uint32_t Bih[2][4][4];   // [kt][nt2(n16)][frag]
    #pragma unroll
    for (int kt = 0; kt < 2; kt++)
        #pragma unroll
        for (int nt2 = 0; nt2 < 4; nt2++)
            LDSM4(Bih[kt][nt2], sb + SM_WIH +
                  (uint32_t)((n0 + nt2 * 16 + rowB) * 64 + (((kt * 2 + csB) ^ l3) << 4)));
    uint32_t Bhh[4][4][4];   // [kt 0..3][nt2][frag]
    #pragma unroll
    for (int kt = 0; kt < 4; kt++)
        #pragma unroll
        for (int nt2 = 0; nt2 < 4; nt2++)
            LDSM4(Bhh[kt][nt2], sb + SM_WHH +
                  (uint32_t)((n0 + nt2 * 16 + rowB) * 256 + (((kt * 2 + csB) ^ l7) << 4)));

    // ---- x direct-from-global A-fragment row pointers ----
    const float* pr[2][2];  // [mt][lo/hi]
    #pragma unroll
    for (int mt = 0; mt < 2; mt++) {
        pr[mt][0] = x + ((size_t)blockIdx.x * 64 + m0 + mt * 16 + g) * 784;
        pr[mt][1] = pr[mt][0] + 8 * 784;
    }

    #define LOAD_AX(Ax, tt)                                                        \
        do {                                                                       \
            _Pragma("unroll")                                                      \
            for (int mt = 0; mt < 2; mt++) {                                       \
                const float* rl = pr[mt][0] + (tt) * 28;                           \
                const float* rh = pr[mt][1] + (tt) * 28;                           \
                _Pragma("unroll")                                                  \
                for (int kt = 0; kt < 2; kt++) {                                   \
                    int c0 = kt * 16 + 2 * q;                                      \
                    (Ax)[mt][kt][0] = ldpair(rl + c0);                             \
                    (Ax)[mt][kt][1] = ldpair(rh + c0);                             \
                    if (kt == 0 || q < 2) {                                        \
                        (Ax)[mt][kt][2] = ldpair(rl + c0 + 8);                     \
                        (Ax)[mt][kt][3] = ldpair(rh + c0 + 8);                     \
                    } else if (q == 2) {   /* cols 28,29 = (1.0, 0) bias */        \
                        (Ax)[mt][kt][2] = 0x00003C00u;                             \
                        (Ax)[mt][kt][3] = 0x00003C00u;                             \
                    } else {                                                       \
                        (Ax)[mt][kt][2] = 0u;                                      \
                        (Ax)[mt][kt][3] = 0u;                                      \
                    }                                                              \
                }                                                                  \
            }                                                                      \
        } while (0)

    float acc[2][8][4];      // [mt][n8 0..7][4] = 64 f32
    uint32_t Ax[2][2][4];    // [mt][kt] = 16 u32

    LOAD_AX(Ax, 0);

    #pragma unroll 1
    for (int t = 0; t < 28; t++) {
        const uint32_t Hrd = (t & 1) ? SM_H1 : SM_H0;
        const uint32_t Hwr = (t & 1) ? SM_H0 : SM_H1;

        #pragma unroll
        for (int mt = 0; mt < 2; mt++)
            #pragma unroll
            for (int nt = 0; nt < 8; nt++)
                #pragma unroll
                for (int j = 0; j < 4; j++) acc[mt][nt][j] = 0.0f;

        // ---- x GEMM (K=32): A and B fully register-resident ----
        #pragma unroll
        for (int kt = 0; kt < 2; kt++)
            #pragma unroll
            for (int mt = 0; mt < 2; mt++)
                #pragma unroll
                for (int nt2 = 0; nt2 < 4; nt2++) {
                    mma_f16(acc[mt][2*nt2],   Ax[mt][kt], Bih[kt][nt2][0], Bih[kt][nt2][1]);
                    mma_f16(acc[mt][2*nt2+1], Ax[mt][kt], Bih[kt][nt2][2], Bih[kt][nt2][3]);
                }

        // ---- hh GEMM (K=128): A via LDSM; B kt<4 cached, kt>=4 LDSM ----
        if (t > 0) {
            #pragma unroll
            for (int kt = 0; kt < 8; kt++) {
                uint32_t A[2][4];
                #pragma unroll
                for (int mt = 0; mt < 2; mt++)
                    LDSM4(A[mt], sb + Hrd +
                          (uint32_t)((m0 + mt * 16 + rowA) * 256 + (((kt * 2 + csA) ^ l7) << 4)));
                if (kt < 4) {
                    #pragma unroll
                    for (int mt = 0; mt < 2; mt++)
                        #pragma unroll
                        for (int nt2 = 0; nt2 < 4; nt2++) {
                            mma_f16(acc[mt][2*nt2],   A[mt], Bhh[kt][nt2][0], Bhh[kt][nt2][1]);
                            mma_f16(acc[mt][2*nt2+1], A[mt], Bhh[kt][nt2][2], Bhh[kt][nt2][3]);
                        }
                } else {
                    uint32_t Bt[4][4];
                    #pragma unroll
                    for (int nt2 = 0; nt2 < 4; nt2++)
                        LDSM4(Bt[nt2], sb + SM_WHH +
                              (uint32_t)((n0 + nt2 * 16 + rowB) * 256 + (((kt * 2 + csB) ^ l7) << 4)));
                    #pragma unroll
                    for (int mt = 0; mt < 2; mt++)
                        #pragma unroll
                        for (int nt2 = 0; nt2 < 4; nt2++) {
                            mma_f16(acc[mt][2*nt2],   A[mt], Bt[nt2][0], Bt[nt2][1]);
                            mma_f16(acc[mt][2*nt2+1], A[mt], Bt[nt2][2], Bt[nt2][3]);
                        }
                }
            }
        }

        // prefetch x(t+1) A-fragments (LDG in flight under epilogue)
        if (t < 27) LOAD_AX(Ax, t + 1);

        if (t < 27) {
            // h(t+1) = tanh.approx(acc) -> fp16 into Hwr ping-pong
            #pragma unroll
            for (int mt = 0; mt < 2; mt++)
                #pragma unroll
                for (int nt = 0; nt < 8; nt++) {
                    const float* c = acc[mt][nt];
                    int r0 = m0 + mt * 16 + g;
                    int r1 = r0 + 8;
                    int chunk = (n0 >> 3) + nt;
                    uint32_t b0 = (uint32_t)(r0 * 256 + ((chunk ^ (r0 & 7)) << 4) + q * 4);
                    uint32_t b1 = (uint32_t)(r1 * 256 + ((chunk ^ (r1 & 7)) << 4) + q * 4);
                    *(uint32_t*)(smem + Hwr + b0) = packh(tanh_fast(c[0]), tanh_fast(c[1]));
                    *(uint32_t*)(smem + Hwr + b1) = packh(tanh_fast(c[2]), tanh_fast(c[3]));
                }
        } else {
            // final step: accurate tanh, fp32 h28 over dead W_hh; barrier first
            __syncthreads();
            float* h32 = (float*)smem;
            #pragma unroll
            for (int mt = 0; mt < 2; mt++)
                #pragma unroll
                for (int nt = 0; nt < 8; nt++) {
                    const float* c = acc[mt][nt];
                    int r0 = m0 + mt * 16 + g;
                    int col = n0 + nt * 8 + 2 * q;
                    *(float2*)(h32 + r0 * 132 + col)       = make_float2(tanh_acc(c[0]), tanh_acc(c[1]));
                    *(float2*)(h32 + (r0 + 8) * 132 + col) = make_float2(tanh_acc(c[2]), tanh_acc(c[3]));
                }
        }
        __syncthreads();
    }

    // ---- fc: out = h28 @ W_fc^T + b_fc (fp32 SIMT, 128 threads) ----
    {
        const float* h32  = (const float*)smem;
        const float* wfc  = (const float*)(smem + SM_WFC);
        const float* bfcS = (const float*)(smem + SM_BFC);
        int r = tid >> 1;
        int c0 = (tid & 1) * 5;
        float s[5];
        #pragma unroll
        for (int j = 0; j < 5; j++) s[j] = bfcS[c0 + j];
        const float4* hr = (const float4*)(h32 + r * 132);
        #pragma unroll 8
        for (int k4 = 0; k4 < 32; k4++) {
            float4 hv = hr[k4];
            #pragma unroll
            for (int j = 0; j < 5; j++) {
                float4 wv = ((const float4*)(wfc + (c0 + j) * 128))[k4];
                s[j] += hv.x * wv.x + hv.y * wv.y + hv.z * wv.z + hv.w * wv.w;
            }
        }
        float* o = out + ((size_t)blockIdx.x * 64 + r) * 10 + c0;
        #pragma unroll
        for (int j = 0; j < 5; j++) o[j] = s[j];
    }
}

extern "C" void kernel_launch(void* const* d_in, const int* in_sizes, int n_in,
                              void* d_out, int out_size) {
    const float* x   = (const float*)d_in[0];
    const float* Wih = (const float*)d_in[1];
    const float* Whh = (const float*)d_in[2];
    const float* bih = (const float*)d_in[3];
    const float* bhh = (const float*)d_in[4];
    const float* Wfc = (const float*)d_in[5];
    const float* bfc = (const float*)d_in[6];
    float* out = (float*)d_out;

    cudaFuncSetAttribute(SimpleRNN_fused_kernel,
                         cudaFuncAttributeMaxDynamicSharedMemorySize, SM_TOTAL);
    SimpleRNN_fused_kernel<<<256, 128, SM_TOTAL>>>(x, Wih, Whh, bih, bhh, Wfc, bfc, out);
}